// round 14
// baseline (speedup 1.0000x reference)
#include <cuda_runtime.h>
#include <cstdint>
#include <cuda_fp16.h>
#include <mma.h>
#include <math.h>

using namespace nvcuda;

#define BATCH   8
#define L_SEQ   680
#define NHEADS  24
#define HDIM    64
#define CDIM    1536
#define MROWS   (BATCH * L_SEQ)      // 5440
#define QKVN    (3 * CDIM)           // 4608

// ---------------- GEMM tiling (fp16 HMMA m16n16k16) ------------------------
// CTA 256x128x64, 8 warps (64x64 warp tiles), 2-stage cp.async double buffer,
// ONE __syncthreads per k-tile (loads issued post-barrier).
#define GBM 256
#define GBN 128
#define HBK 64                          // halves per k-tile
#define NSTAGE 2
#define HTLD 72                         // 64 + 8 pad halves
#define SROWS (GBM + GBN)               // 384 rows (A then B)
#define STAGE_H (SROWS * HTLD)          // 27648 halves / stage
#define EPLD 132
#define GEMM_THREADS 256
#define GEMM_SMEM_BYTES (NSTAGE * STAGE_H * 2)   // 110592

// ---------------- attention tiling (fp16 HMMA flash) -----------------------
#define AQ 128
#define AK 64
#define QLD 72
#define SLD 68
#define ATHREADS 256
#define OFF_Q   0
#define OFF_K   (OFF_Q + AQ * QLD * 2)
#define OFF_V   (OFF_K + 2 * AK * QLD * 2)
#define OFF_S   (OFF_V + 2 * AK * QLD * 2)
#define OFF_P   (OFF_S + AQ * SLD * 4)
#define OFF_O   (OFF_P + AQ * QLD * 2)
#define ATT_SMEM_BYTES (OFF_O + AQ * SLD * 4)     // 143360

__device__ float  g_bias[QKVN];
__device__ __half g_xh   [MROWS * CDIM];
__device__ __half g_wqkvh[QKVN * CDIM];
__device__ __half g_woh  [CDIM * CDIM];
__device__ __half g_qkvh [MROWS * QKVN];
__device__ __half g_aoh  [MROWS * CDIM];

// ---------------------------------------------------------------------------
__global__ void bias_compose_kernel(const float* __restrict__ qb,
                                    const float* __restrict__ vb) {
    int n = blockIdx.x * 256 + threadIdx.x;
    if (n >= QKVN) return;
    float v = 0.f;
    if (n < CDIM)            v = qb[n];
    else if (n >= 2 * CDIM)  v = vb[n - 2 * CDIM];
    g_bias[n] = v;
}

__global__ __launch_bounds__(256) void round_half_kernel(
    const float* __restrict__ x, __half* __restrict__ y, int n4)
{
    int i = blockIdx.x * 256 + threadIdx.x;
    if (i >= n4) return;
    float4 v = ((const float4*)x)[i];
    ((__half2*)y)[2 * i + 0] = __floats2half2_rn(v.x, v.y);
    ((__half2*)y)[2 * i + 1] = __floats2half2_rn(v.z, v.w);
}

// ---------------------------------------------------------------------------
__device__ __forceinline__ void cp_async16h(__half* smem, const __half* g, bool pred) {
    unsigned int saddr = (unsigned int)__cvta_generic_to_shared(smem);
    int sz = pred ? 16 : 0;
    asm volatile("cp.async.cg.shared.global [%0], [%1], 16, %2;\n"
                 :: "r"(saddr), "l"(g), "r"(sz));
}
__device__ __forceinline__ void cp_commit() {
    asm volatile("cp.async.commit_group;\n");
}
template <int N>
__device__ __forceinline__ void cp_wait() {
    asm volatile("cp.async.wait_group %0;\n" :: "n"(N));
}

// ---------------------------------------------------------------------------
// C[m][n] = sum_k A[m][k]*Bm[n][k] + bias[n] (fp16 HMMA, fp32 accum)
// Output: Cf (fp32) or Ch (half) — exactly one non-null.
// ---------------------------------------------------------------------------
__global__ __launch_bounds__(GEMM_THREADS, 2) void gemm_fp16_bt_bias(
    const __half* __restrict__ A, const __half* __restrict__ Bm,
    const float* __restrict__ bias, float* __restrict__ Cf,
    __half* __restrict__ Ch, int M, int N, int K)
{
    extern __shared__ __half smh[];
    float* smf = reinterpret_cast<float*>(smh);

    const int tid = threadIdx.x;
    const int wid = tid >> 5;
    const int m0  = blockIdx.y * GBM;
    const int n0  = blockIdx.x * GBN;
    const int wm  = wid >> 1;
    const int wn  = wid & 1;

    wmma::fragment<wmma::accumulator, 16, 16, 16, float> acc[4][4];
    #pragma unroll
    for (int i = 0; i < 4; i++)
        #pragma unroll
        for (int j = 0; j < 4; j++)
            wmma::fill_fragment(acc[i][j], 0.0f);

    const int nk = K / HBK;          // 24

    // stage loader: 384 rows x 64 halves = 3072 16B-chunks, 12/thread
    auto load_stage = [&](int s, int kc) {
        __half* base = smh + s * STAGE_H;
        #pragma unroll
        for (int r = 0; r < 12; r++) {
            int u    = tid + r * GEMM_THREADS;   // 0..3071
            int row  = u >> 3;
            int slot = u & 7;
            __half* dst = base + row * HTLD + slot * 8;
            if (row < GBM) {
                cp_async16h(dst, A + (size_t)(m0 + row) * K + kc + slot * 8,
                            (m0 + row) < M);
            } else {
                cp_async16h(dst, Bm + (size_t)(n0 + row - GBM) * K + kc + slot * 8,
                            true);
            }
        }
    };

    load_stage(0, 0);
    cp_commit();

    for (int kt = 0; kt < nk; kt++) {
        cp_wait<0>();            // stage kt complete (only pending group)
        __syncthreads();         // visible to all; all done computing kt-1

        if (kt + 1 < nk) {       // safe: buffer (kt+1)&1 last read in kt-1
            load_stage((kt + 1) & 1, (kt + 1) * HBK);
            cp_commit();
        }

        const __half* ab = smh + (kt & 1) * STAGE_H;
        const __half* bb = ab + GBM * HTLD;

        #pragma unroll
        for (int ks = 0; ks < 4; ks++) {
            wmma::fragment<wmma::matrix_a, 16, 16, 16, half,
                           wmma::row_major> af[4];
            wmma::fragment<wmma::matrix_b, 16, 16, 16, half,
                           wmma::col_major> bf[4];
            #pragma unroll
            for (int i = 0; i < 4; i++)
                wmma::load_matrix_sync(af[i],
                    ab + (wm * 64 + i * 16) * HTLD + ks * 16, HTLD);
            #pragma unroll
            for (int j = 0; j < 4; j++)
                wmma::load_matrix_sync(bf[j],
                    bb + (wn * 64 + j * 16) * HTLD + ks * 16, HTLD);
            #pragma unroll
            for (int i = 0; i < 4; i++)
                #pragma unroll
                for (int j = 0; j < 4; j++)
                    wmma::mma_sync(acc[i][j], af[i], bf[j], acc[i][j]);
        }
    }

    // epilogue: two 128-row passes through smem, bias, write (fp32 or half)
    #pragma unroll
    for (int pass = 0; pass < 2; pass++) {
        __syncthreads();
        if ((wm >> 1) == pass) {
            #pragma unroll
            for (int i = 0; i < 4; i++)
                #pragma unroll
                for (int j = 0; j < 4; j++)
                    wmma::store_matrix_sync(
                        smf + ((wm & 1) * 64 + i * 16) * EPLD + wn * 64 + j * 16,
                        acc[i][j], EPLD, wmma::mem_row_major);
        }
        __syncthreads();
        {
            int r = tid >> 1;
            int cseg = (tid & 1) * 64;
            int m = m0 + pass * 128 + r;
            if (m < M) {
                const float* ep = smf + r * EPLD + cseg;
                const float* bp = bias + n0 + cseg;
                if (Cf) {
                    float* cp = Cf + (size_t)m * N + n0 + cseg;
                    #pragma unroll
                    for (int j = 0; j < 16; j++) {
                        float4 v = *(const float4*)(ep + j * 4);
                        v.x += bp[j * 4 + 0]; v.y += bp[j * 4 + 1];
                        v.z += bp[j * 4 + 2]; v.w += bp[j * 4 + 3];
                        *(float4*)(cp + j * 4) = v;
                    }
                } else {
                    __half2* cp = (__half2*)(Ch + (size_t)m * N + n0 + cseg);
                    #pragma unroll
                    for (int j = 0; j < 16; j++) {
                        float4 v = *(const float4*)(ep + j * 4);
                        cp[2 * j + 0] = __floats2half2_rn(v.x + bp[j*4+0],
                                                          v.y + bp[j*4+1]);
                        cp[2 * j + 1] = __floats2half2_rn(v.z + bp[j*4+2],
                                                          v.w + bp[j*4+3]);
                    }
                }
            }
        }
    }
}

// ---------------------------------------------------------------------------
// RoPE in place over q and k components of g_qkvh (half in/out, fp32 math).
// ---------------------------------------------------------------------------
__global__ __launch_bounds__(256) void rope_kernel(
    const float* __restrict__ pos, __half* __restrict__ qkvh)
{
    int u = blockIdx.x * 256 + threadIdx.x;
    const int total = MROWS * 2 * NHEADS * 8;
    if (u >= total) return;
    int quad = u & 7;  u >>= 3;
    int h    = u % NHEADS; u /= NHEADS;
    int comp = u & 1;  int row = u >> 1;
    int d = quad * 4;

    __half* base = qkvh + (size_t)row * QKVN + comp * CDIM + h * HDIM;
    float p0 = pos[(size_t)row * 2 + 0];
    float p1 = pos[(size_t)row * 2 + 1];

    __half2 lo01 = *(__half2*)(base + d);
    __half2 lo23 = *(__half2*)(base + d + 2);
    __half2 hi01 = *(__half2*)(base + d + 32);
    __half2 hi23 = *(__half2*)(base + d + 32 + 2);
    float lo[4] = { __half2float(lo01.x), __half2float(lo01.y),
                    __half2float(lo23.x), __half2float(lo23.y) };
    float hi[4] = { __half2float(hi01.x), __half2float(hi01.y),
                    __half2float(hi23.x), __half2float(hi23.y) };
    float nlo[4], nhi[4];
    #pragma unroll
    for (int j = 0; j < 4; j++) {
        int fi = (d + j) & 15;
        float invf = __expf(-0.5756462732485115f * (float)fi);
        float sa, ca, sb, cb;
        __sincosf(p0 * invf, &sa, &ca);
        __sincosf(p1 * invf, &sb, &cb);
        nlo[j] = lo[j] * ca - hi[j] * sa;
        nhi[j] = hi[j] * cb + lo[j] * sb;
    }
    *(__half2*)(base + d)          = __floats2half2_rn(nlo[0], nlo[1]);
    *(__half2*)(base + d + 2)      = __floats2half2_rn(nlo[2], nlo[3]);
    *(__half2*)(base + d + 32)     = __floats2half2_rn(nhi[0], nhi[1]);
    *(__half2*)(base + d + 32 + 2) = __floats2half2_rn(nhi[2], nhi[3]);
}

// ---------------------------------------------------------------------------
// Flash attention: fp16 wmma S/PV, fp32 softmax+O.
// ONE __syncthreads per k-tile: the S -> softmax -> PV chain is warp-private
// (warp w owns q-rows 16w..16w+15 in every phase); only K/V staging is
// CTA-wide. __syncwarp() fences smem between warp-private phases.
// ---------------------------------------------------------------------------
__global__ __launch_bounds__(ATHREADS) void attn_fp16_kernel(
    const __half* __restrict__ qkvh, __half* __restrict__ aoh)
{
    extern __shared__ char smb[];
    __half* Qs = (__half*)(smb + OFF_Q);
    __half* Ks = (__half*)(smb + OFF_K);
    __half* Vs = (__half*)(smb + OFF_V);
    float*  Ss = (float* )(smb + OFF_S);
    __half* Ps = (__half*)(smb + OFF_P);
    float*  Os = (float* )(smb + OFF_O);

    const int qt = blockIdx.x, h = blockIdx.y, b = blockIdx.z;
    const int tid = threadIdx.x;
    const int wid = tid >> 5;
    const int q0  = qt * AQ;
    const int r   = tid >> 1;
    const int cb0 = (tid & 1) * 32;

    #pragma unroll
    for (int c = 0; c < 4; c++) {
        int u = tid + c * ATHREADS;
        int row = u >> 3, slot = u & 7;
        int lg = q0 + row;
        cp_async16h(Qs + row * QLD + slot * 8,
                    qkvh + (size_t)(b * L_SEQ + (lg < L_SEQ ? lg : 0)) * QKVN
                         + h * HDIM + slot * 8,
                    lg < L_SEQ);
    }
    cp_commit();

    #pragma unroll
    for (int c = 0; c < 8; c++) {
        int u = tid + c * ATHREADS;
        float* p = Os + (u >> 4) * SLD + (u & 15) * 4;
        p[0] = 0.f; p[1] = 0.f; p[2] = 0.f; p[3] = 0.f;
    }

    auto load_kv = [&](int bf, int k0) {
        __half* kd = Ks + bf * AK * QLD;
        __half* vd = Vs + bf * AK * QLD;
        #pragma unroll
        for (int c = 0; c < 2; c++) {
            int u = tid + c * ATHREADS;
            int row = u >> 3, slot = u & 7;
            int lg = k0 + row;
            bool ok = lg < L_SEQ;
            size_t gro = (size_t)(b * L_SEQ + (ok ? lg : 0)) * QKVN + h * HDIM
                         + slot * 8;
            cp_async16h(kd + row * QLD + slot * 8, qkvh + gro + CDIM, ok);
            cp_async16h(vd + row * QLD + slot * 8, qkvh + gro + 2 * CDIM, ok);
        }
    };

    load_kv(0, 0);
    cp_commit();

    float m_run = -1e30f, l_run = 0.f;
    const int NT = (L_SEQ + AK - 1) / AK;   // 11

    for (int kt = 0; kt < NT; kt++) {
        int k0 = kt * AK;
        cp_wait<0>();
        __syncthreads();          // K/V(kt) ready; all warps done with kt-1

        if (kt + 1 < NT) {        // buffer (kt+1)&1 last read in PV of kt-1
            load_kv((kt + 1) & 1, k0 + AK);
            cp_commit();
        }

        const __half* kb = Ks + (kt & 1) * AK * QLD;
        const __half* vb = Vs + (kt & 1) * AK * QLD;

        // ---- S = Q K^T (warp-private rows) ----
        {
            const int wr0 = wid * 16;
            wmma::fragment<wmma::accumulator, 16, 16, 16, float> acc[4];
            #pragma unroll
            for (int c = 0; c < 4; c++) wmma::fill_fragment(acc[c], 0.0f);
            #pragma unroll
            for (int ks = 0; ks < 4; ks++) {
                wmma::fragment<wmma::matrix_a, 16, 16, 16, half,
                               wmma::row_major> af;
                wmma::load_matrix_sync(af, Qs + wr0 * QLD + ks * 16, QLD);
                #pragma unroll
                for (int c = 0; c < 4; c++) {
                    wmma::fragment<wmma::matrix_b, 16, 16, 16, half,
                                   wmma::col_major> bf;
                    wmma::load_matrix_sync(bf, kb + (c * 16) * QLD + ks * 16, QLD);
                    wmma::mma_sync(acc[c], af, bf, acc[c]);
                }
            }
            #pragma unroll
            for (int c = 0; c < 4; c++)
                wmma::store_matrix_sync(Ss + wr0 * SLD + c * 16, acc[c],
                                        SLD, wmma::mem_row_major);
        }
        __syncwarp();             // S rows visible within owning warp

        // ---- online softmax (2 threads per row; row r owned by this warp) --
        {
            float* srow = Ss + r * SLD + cb0;
            float s[32];
            float mx = -1e30f;
            #pragma unroll
            for (int c = 0; c < 32; c++) {
                float v = srow[c] * 0.125f;
                if (k0 + cb0 + c >= L_SEQ) v = -1e30f;
                s[c] = v;
                mx = fmaxf(mx, v);
            }
            mx = fmaxf(mx, __shfl_xor_sync(0xffffffffu, mx, 1));
            float m_new = fmaxf(m_run, mx);
            float alpha = __expf(m_run - m_new);
            float rsum = 0.f;
            __half2* prow = (__half2*)(Ps + r * QLD + cb0);
            #pragma unroll
            for (int c = 0; c < 32; c += 2) {
                float p0v = __expf(s[c]     - m_new);
                float p1v = __expf(s[c + 1] - m_new);
                rsum += p0v + p1v;
                prow[c >> 1] = __floats2half2_rn(p0v, p1v);
            }
            rsum += __shfl_xor_sync(0xffffffffu, rsum, 1);
            l_run = l_run * alpha + rsum;
            m_run = m_new;
            float* orow = Os + r * SLD + cb0;
            #pragma unroll
            for (int c = 0; c < 32; c += 4) {
                float4 v = *(float4*)(orow + c);
                v.x *= alpha; v.y *= alpha; v.z *= alpha; v.w *= alpha;
                *(float4*)(orow + c) = v;
            }
        }
        __syncwarp();             // P + rescaled O visible within warp

        // ---- O += P V (warp-private rows) ----
        {
            const int wr0 = wid * 16;
            wmma::fragment<wmma::accumulator, 16, 16, 16, float> acc[4];
            #pragma unroll
            for (int c = 0; c < 4; c++)
                wmma::load_matrix_sync(acc[c], Os + wr0 * SLD + c * 16,
                                       SLD, wmma::mem_row_major);
            #pragma unroll
            for (int ks = 0; ks < 4; ks++) {
                wmma::fragment<wmma::matrix_a, 16, 16, 16, half,
                               wmma::row_major> af;
                wmma::load_matrix_sync(af, Ps + wr0 * QLD + ks * 16, QLD);
                #pragma unroll
                for (int c = 0; c < 4; c++) {
                    wmma::fragment<wmma::matrix_b, 16, 16, 16, half,
                                   wmma::row_major> bf;
                    wmma::load_matrix_sync(bf, vb + (ks * 16) * QLD + c * 16, QLD);
                    wmma::mma_sync(acc[c], af, bf, acc[c]);
                }
            }
            #pragma unroll
            for (int c = 0; c < 4; c++)
                wmma::store_matrix_sync(Os + wr0 * SLD + c * 16, acc[c],
                                        SLD, wmma::mem_row_major);
        }
        __syncwarp();             // O store visible before next-iter acc load
    }
    __syncthreads();

    {
        int lg = q0 + r;
        if (lg < L_SEQ) {
            float inv_l = 1.0f / l_run;
            const float* orow = Os + r * SLD + cb0;
            __half2* dst = (__half2*)(aoh + (size_t)(b * L_SEQ + lg) * CDIM
                                      + h * HDIM + cb0);
            #pragma unroll
            for (int c = 0; c < 32; c += 2)
                dst[c >> 1] = __floats2half2_rn(orow[c] * inv_l,
                                                orow[c + 1] * inv_l);
        }
    }
}

// ---------------------------------------------------------------------------
extern "C" void kernel_launch(void* const* d_in, const int* in_sizes, int n_in,
                              void* d_out, int out_size)
{
    const float* x    = (const float*)d_in[0];
    const float* pos  = (const float*)d_in[1];
    const float* wqkv = (const float*)d_in[2];
    const float* qb   = (const float*)d_in[3];
    const float* vb   = (const float*)d_in[4];
    const float* wo   = (const float*)d_in[5];
    const float* bo   = (const float*)d_in[6];
    float* out = (float*)d_out;

    float *bias_p;
    __half *xh_p, *wqkvh_p, *woh_p, *qkvh_p, *aoh_p;
    cudaGetSymbolAddress((void**)&bias_p,  g_bias);
    cudaGetSymbolAddress((void**)&xh_p,    g_xh);
    cudaGetSymbolAddress((void**)&wqkvh_p, g_wqkvh);
    cudaGetSymbolAddress((void**)&woh_p,   g_woh);
    cudaGetSymbolAddress((void**)&qkvh_p,  g_qkvh);
    cudaGetSymbolAddress((void**)&aoh_p,   g_aoh);

    bias_compose_kernel<<<(QKVN + 255)/256, 256>>>(qb, vb);

    {
        int n4 = (MROWS * CDIM) / 4;
        round_half_kernel<<<(n4 + 255)/256, 256>>>(x, xh_p, n4);
        n4 = (QKVN * CDIM) / 4;
        round_half_kernel<<<(n4 + 255)/256, 256>>>(wqkv, wqkvh_p, n4);
        n4 = (CDIM * CDIM) / 4;
        round_half_kernel<<<(n4 + 255)/256, 256>>>(wo, woh_p, n4);
    }

    cudaFuncSetAttribute(gemm_fp16_bt_bias,
                         cudaFuncAttributeMaxDynamicSharedMemorySize, GEMM_SMEM_BYTES);

    dim3 g1(QKVN / GBN, (MROWS + GBM - 1) / GBM);
    gemm_fp16_bt_bias<<<g1, GEMM_THREADS, GEMM_SMEM_BYTES>>>(
        xh_p, wqkvh_p, bias_p, nullptr, qkvh_p, MROWS, QKVN, CDIM);

    {
        int total = MROWS * 2 * NHEADS * 8;
        rope_kernel<<<(total + 255)/256, 256>>>(pos, qkvh_p);
    }

    cudaFuncSetAttribute(attn_fp16_kernel,
                         cudaFuncAttributeMaxDynamicSharedMemorySize, ATT_SMEM_BYTES);
    attn_fp16_kernel<<<dim3((L_SEQ + AQ - 1)/AQ, NHEADS, BATCH), ATHREADS,
                       ATT_SMEM_BYTES>>>(qkvh_p, aoh_p);

    dim3 g2(CDIM / GBN, (MROWS + GBM - 1) / GBM);
    gemm_fp16_bt_bias<<<g2, GEMM_THREADS, GEMM_SMEM_BYTES>>>(
        aoh_p, woh_p, bo, out, nullptr, MROWS, CDIM, CDIM);
}

// round 15
// speedup vs baseline: 1.5817x; 1.5817x over previous
#include <cuda_runtime.h>
#include <cstdint>
#include <cuda_fp16.h>
#include <mma.h>
#include <math.h>

using namespace nvcuda;

#define BATCH   8
#define L_SEQ   680
#define NHEADS  24
#define HDIM    64
#define CDIM    1536
#define MROWS   (BATCH * L_SEQ)      // 5440
#define QKVN    (3 * CDIM)           // 4608

// ---------------- GEMM tiling (fp16 HMMA m16n16k16) ------------------------
// R12/R13-proven config: CTA 256x128x32, 8 warps (64x64 warp tiles),
// 3-stage cp.async ring, cp_wait<1> (2 groups outstanding).
#define GBM 256
#define GBN 128
#define HBK 32
#define NSTAGE 3
#define HTLD 40
#define SROWS (GBM + GBN)
#define STAGE_H (SROWS * HTLD)
#define EPLD 132
#define GEMM_THREADS 256
#define GEMM_SMEM_BYTES (NSTAGE * STAGE_H * 2)   // 92160

// ---------------- attention tiling (fp16 HMMA flash) -----------------------
#define AQ 128
#define AK 64
#define QLD 72
#define SLD 68
#define ATHREADS 256
#define OFF_Q   0
#define OFF_K   (OFF_Q + AQ * QLD * 2)
#define OFF_V   (OFF_K + 2 * AK * QLD * 2)
#define OFF_S   (OFF_V + 2 * AK * QLD * 2)
#define OFF_P   (OFF_S + AQ * SLD * 4)
#define OFF_O   (OFF_P + AQ * QLD * 2)
#define ATT_SMEM_BYTES (OFF_O + AQ * SLD * 4)     // 143360

__device__ float  g_bias[QKVN];
__device__ __half g_xh   [MROWS * CDIM];
__device__ __half g_wqkvh[QKVN * CDIM];
__device__ __half g_woh  [CDIM * CDIM];
__device__ __half g_qkvh [MROWS * QKVN];
__device__ __half g_aoh  [MROWS * CDIM];

// ---------------------------------------------------------------------------
__global__ void bias_compose_kernel(const float* __restrict__ qb,
                                    const float* __restrict__ vb) {
    int n = blockIdx.x * 256 + threadIdx.x;
    if (n >= QKVN) return;
    float v = 0.f;
    if (n < CDIM)            v = qb[n];
    else if (n >= 2 * CDIM)  v = vb[n - 2 * CDIM];
    g_bias[n] = v;
}

__global__ __launch_bounds__(256) void round_half_kernel(
    const float* __restrict__ x, __half* __restrict__ y, int n4)
{
    int i = blockIdx.x * 256 + threadIdx.x;
    if (i >= n4) return;
    float4 v = ((const float4*)x)[i];
    ((__half2*)y)[2 * i + 0] = __floats2half2_rn(v.x, v.y);
    ((__half2*)y)[2 * i + 1] = __floats2half2_rn(v.z, v.w);
}

// ---------------------------------------------------------------------------
__device__ __forceinline__ void cp_async16h(__half* smem, const __half* g, bool pred) {
    unsigned int saddr = (unsigned int)__cvta_generic_to_shared(smem);
    int sz = pred ? 16 : 0;
    asm volatile("cp.async.cg.shared.global [%0], [%1], 16, %2;\n"
                 :: "r"(saddr), "l"(g), "r"(sz));
}
__device__ __forceinline__ void cp_commit() {
    asm volatile("cp.async.commit_group;\n");
}
template <int N>
__device__ __forceinline__ void cp_wait() {
    asm volatile("cp.async.wait_group %0;\n" :: "n"(N));
}

// ---------------------------------------------------------------------------
// C[m][n] = sum_k A[m][k]*Bm[n][k] + bias[n] (fp16 HMMA, fp32 accum)
// Output: Cf (fp32) or Ch (half) — exactly one non-null.  [R12-proven]
// ---------------------------------------------------------------------------
__global__ __launch_bounds__(GEMM_THREADS) void gemm_fp16_bt_bias(
    const __half* __restrict__ A, const __half* __restrict__ Bm,
    const float* __restrict__ bias, float* __restrict__ Cf,
    __half* __restrict__ Ch, int M, int N, int K)
{
    extern __shared__ __half smh[];
    float* smf = reinterpret_cast<float*>(smh);

    const int tid = threadIdx.x;
    const int wid = tid >> 5;
    const int m0  = blockIdx.y * GBM;
    const int n0  = blockIdx.x * GBN;
    const int wm  = wid >> 1;
    const int wn  = wid & 1;

    wmma::fragment<wmma::accumulator, 16, 16, 16, float> acc[4][4];
    #pragma unroll
    for (int i = 0; i < 4; i++)
        #pragma unroll
        for (int j = 0; j < 4; j++)
            wmma::fill_fragment(acc[i][j], 0.0f);

    const int nk = K / HBK;

    auto load_stage = [&](int s, int kc) {
        __half* base = smh + s * STAGE_H;
        #pragma unroll
        for (int r = 0; r < 6; r++) {
            int u    = tid + r * GEMM_THREADS;
            int row  = u >> 2;
            int slot = u & 3;
            __half* dst = base + row * HTLD + slot * 8;
            if (row < GBM) {
                cp_async16h(dst, A + (size_t)(m0 + row) * K + kc + slot * 8,
                            (m0 + row) < M);
            } else {
                cp_async16h(dst, Bm + (size_t)(n0 + row - GBM) * K + kc + slot * 8,
                            true);
            }
        }
    };

    load_stage(0, 0);        cp_commit();
    load_stage(1, HBK);      cp_commit();

    for (int kt = 0; kt < nk; kt++) {
        cp_wait<1>();
        __syncthreads();

        if (kt + 2 < nk) {
            load_stage((kt + 2) % NSTAGE, (kt + 2) * HBK);
            cp_commit();
        }

        const __half* ab = smh + (kt % NSTAGE) * STAGE_H;
        const __half* bb = ab + GBM * HTLD;

        #pragma unroll
        for (int ks = 0; ks < 2; ks++) {
            wmma::fragment<wmma::matrix_a, 16, 16, 16, half,
                           wmma::row_major> af[4];
            wmma::fragment<wmma::matrix_b, 16, 16, 16, half,
                           wmma::col_major> bf[4];
            #pragma unroll
            for (int i = 0; i < 4; i++)
                wmma::load_matrix_sync(af[i],
                    ab + (wm * 64 + i * 16) * HTLD + ks * 16, HTLD);
            #pragma unroll
            for (int j = 0; j < 4; j++)
                wmma::load_matrix_sync(bf[j],
                    bb + (wn * 64 + j * 16) * HTLD + ks * 16, HTLD);
            #pragma unroll
            for (int i = 0; i < 4; i++)
                #pragma unroll
                for (int j = 0; j < 4; j++)
                    wmma::mma_sync(acc[i][j], af[i], bf[j], acc[i][j]);
        }
    }

    #pragma unroll
    for (int pass = 0; pass < 2; pass++) {
        __syncthreads();
        if ((wm >> 1) == pass) {
            #pragma unroll
            for (int i = 0; i < 4; i++)
                #pragma unroll
                for (int j = 0; j < 4; j++)
                    wmma::store_matrix_sync(
                        smf + ((wm & 1) * 64 + i * 16) * EPLD + wn * 64 + j * 16,
                        acc[i][j], EPLD, wmma::mem_row_major);
        }
        __syncthreads();
        {
            int r = tid >> 1;
            int cseg = (tid & 1) * 64;
            int m = m0 + pass * 128 + r;
            if (m < M) {
                const float* ep = smf + r * EPLD + cseg;
                const float* bp = bias + n0 + cseg;
                if (Cf) {
                    float* cp = Cf + (size_t)m * N + n0 + cseg;
                    #pragma unroll
                    for (int j = 0; j < 16; j++) {
                        float4 v = *(const float4*)(ep + j * 4);
                        v.x += bp[j * 4 + 0]; v.y += bp[j * 4 + 1];
                        v.z += bp[j * 4 + 2]; v.w += bp[j * 4 + 3];
                        *(float4*)(cp + j * 4) = v;
                    }
                } else {
                    __half2* cp = (__half2*)(Ch + (size_t)m * N + n0 + cseg);
                    #pragma unroll
                    for (int j = 0; j < 16; j++) {
                        float4 v = *(const float4*)(ep + j * 4);
                        cp[2 * j + 0] = __floats2half2_rn(v.x + bp[j*4+0],
                                                          v.y + bp[j*4+1]);
                        cp[2 * j + 1] = __floats2half2_rn(v.z + bp[j*4+2],
                                                          v.w + bp[j*4+3]);
                    }
                }
            }
        }
    }
}

// ---------------------------------------------------------------------------
// RoPE in place over q and k components of g_qkvh (half in/out, fp32 math).
// ---------------------------------------------------------------------------
__global__ __launch_bounds__(256) void rope_kernel(
    const float* __restrict__ pos, __half* __restrict__ qkvh)
{
    int u = blockIdx.x * 256 + threadIdx.x;
    const int total = MROWS * 2 * NHEADS * 8;
    if (u >= total) return;
    int quad = u & 7;  u >>= 3;
    int h    = u % NHEADS; u /= NHEADS;
    int comp = u & 1;  int row = u >> 1;
    int d = quad * 4;

    __half* base = qkvh + (size_t)row * QKVN + comp * CDIM + h * HDIM;
    float p0 = pos[(size_t)row * 2 + 0];
    float p1 = pos[(size_t)row * 2 + 1];

    __half2 lo01 = *(__half2*)(base + d);
    __half2 lo23 = *(__half2*)(base + d + 2);
    __half2 hi01 = *(__half2*)(base + d + 32);
    __half2 hi23 = *(__half2*)(base + d + 32 + 2);
    float lo[4] = { __half2float(lo01.x), __half2float(lo01.y),
                    __half2float(lo23.x), __half2float(lo23.y) };
    float hi[4] = { __half2float(hi01.x), __half2float(hi01.y),
                    __half2float(hi23.x), __half2float(hi23.y) };
    float nlo[4], nhi[4];
    #pragma unroll
    for (int j = 0; j < 4; j++) {
        int fi = (d + j) & 15;
        float invf = __expf(-0.5756462732485115f * (float)fi);
        float sa, ca, sb, cb;
        __sincosf(p0 * invf, &sa, &ca);
        __sincosf(p1 * invf, &sb, &cb);
        nlo[j] = lo[j] * ca - hi[j] * sa;
        nhi[j] = hi[j] * cb + lo[j] * sb;
    }
    *(__half2*)(base + d)          = __floats2half2_rn(nlo[0], nlo[1]);
    *(__half2*)(base + d + 2)      = __floats2half2_rn(nlo[2], nlo[3]);
    *(__half2*)(base + d + 32)     = __floats2half2_rn(nhi[0], nhi[1]);
    *(__half2*)(base + d + 32 + 2) = __floats2half2_rn(nhi[2], nhi[3]);
}

// ---------------------------------------------------------------------------
// Flash attention: fp16 wmma S/PV, fp32 softmax+O.
// ONE __syncthreads per k-tile; S->softmax->PV chain is warp-private.
// ---------------------------------------------------------------------------
__global__ __launch_bounds__(ATHREADS) void attn_fp16_kernel(
    const __half* __restrict__ qkvh, __half* __restrict__ aoh)
{
    extern __shared__ char smb[];
    __half* Qs = (__half*)(smb + OFF_Q);
    __half* Ks = (__half*)(smb + OFF_K);
    __half* Vs = (__half*)(smb + OFF_V);
    float*  Ss = (float* )(smb + OFF_S);
    __half* Ps = (__half*)(smb + OFF_P);
    float*  Os = (float* )(smb + OFF_O);

    const int qt = blockIdx.x, h = blockIdx.y, b = blockIdx.z;
    const int tid = threadIdx.x;
    const int wid = tid >> 5;
    const int q0  = qt * AQ;
    const int r   = tid >> 1;
    const int cb0 = (tid & 1) * 32;

    #pragma unroll
    for (int c = 0; c < 4; c++) {
        int u = tid + c * ATHREADS;
        int row = u >> 3, slot = u & 7;
        int lg = q0 + row;
        cp_async16h(Qs + row * QLD + slot * 8,
                    qkvh + (size_t)(b * L_SEQ + (lg < L_SEQ ? lg : 0)) * QKVN
                         + h * HDIM + slot * 8,
                    lg < L_SEQ);
    }
    cp_commit();

    #pragma unroll
    for (int c = 0; c < 8; c++) {
        int u = tid + c * ATHREADS;
        float* p = Os + (u >> 4) * SLD + (u & 15) * 4;
        p[0] = 0.f; p[1] = 0.f; p[2] = 0.f; p[3] = 0.f;
    }

    auto load_kv = [&](int bf, int k0) {
        __half* kd = Ks + bf * AK * QLD;
        __half* vd = Vs + bf * AK * QLD;
        #pragma unroll
        for (int c = 0; c < 2; c++) {
            int u = tid + c * ATHREADS;
            int row = u >> 3, slot = u & 7;
            int lg = k0 + row;
            bool ok = lg < L_SEQ;
            size_t gro = (size_t)(b * L_SEQ + (ok ? lg : 0)) * QKVN + h * HDIM
                         + slot * 8;
            cp_async16h(kd + row * QLD + slot * 8, qkvh + gro + CDIM, ok);
            cp_async16h(vd + row * QLD + slot * 8, qkvh + gro + 2 * CDIM, ok);
        }
    };

    load_kv(0, 0);
    cp_commit();

    float m_run = -1e30f, l_run = 0.f;
    const int NT = (L_SEQ + AK - 1) / AK;   // 11

    for (int kt = 0; kt < NT; kt++) {
        int k0 = kt * AK;
        cp_wait<0>();
        __syncthreads();          // K/V(kt) ready; all warps done with kt-1

        if (kt + 1 < NT) {
            load_kv((kt + 1) & 1, k0 + AK);
            cp_commit();
        }

        const __half* kb = Ks + (kt & 1) * AK * QLD;
        const __half* vb = Vs + (kt & 1) * AK * QLD;

        // ---- S = Q K^T (warp-private rows) ----
        {
            const int wr0 = wid * 16;
            wmma::fragment<wmma::accumulator, 16, 16, 16, float> acc[4];
            #pragma unroll
            for (int c = 0; c < 4; c++) wmma::fill_fragment(acc[c], 0.0f);
            #pragma unroll
            for (int ks = 0; ks < 4; ks++) {
                wmma::fragment<wmma::matrix_a, 16, 16, 16, half,
                               wmma::row_major> af;
                wmma::load_matrix_sync(af, Qs + wr0 * QLD + ks * 16, QLD);
                #pragma unroll
                for (int c = 0; c < 4; c++) {
                    wmma::fragment<wmma::matrix_b, 16, 16, 16, half,
                                   wmma::col_major> bf;
                    wmma::load_matrix_sync(bf, kb + (c * 16) * QLD + ks * 16, QLD);
                    wmma::mma_sync(acc[c], af, bf, acc[c]);
                }
            }
            #pragma unroll
            for (int c = 0; c < 4; c++)
                wmma::store_matrix_sync(Ss + wr0 * SLD + c * 16, acc[c],
                                        SLD, wmma::mem_row_major);
        }
        __syncwarp();

        // ---- online softmax (2 threads/row; row r owned by this warp) ----
        {
            float* srow = Ss + r * SLD + cb0;
            float s[32];
            float mx = -1e30f;
            #pragma unroll
            for (int c = 0; c < 32; c++) {
                float v = srow[c] * 0.125f;
                if (k0 + cb0 + c >= L_SEQ) v = -1e30f;
                s[c] = v;
                mx = fmaxf(mx, v);
            }
            mx = fmaxf(mx, __shfl_xor_sync(0xffffffffu, mx, 1));
            float m_new = fmaxf(m_run, mx);
            float alpha = __expf(m_run - m_new);
            float rsum = 0.f;
            __half2* prow = (__half2*)(Ps + r * QLD + cb0);
            #pragma unroll
            for (int c = 0; c < 32; c += 2) {
                float p0v = __expf(s[c]     - m_new);
                float p1v = __expf(s[c + 1] - m_new);
                rsum += p0v + p1v;
                prow[c >> 1] = __floats2half2_rn(p0v, p1v);
            }
            rsum += __shfl_xor_sync(0xffffffffu, rsum, 1);
            l_run = l_run * alpha + rsum;
            m_run = m_new;
            float* orow = Os + r * SLD + cb0;
            #pragma unroll
            for (int c = 0; c < 32; c += 4) {
                float4 v = *(float4*)(orow + c);
                v.x *= alpha; v.y *= alpha; v.z *= alpha; v.w *= alpha;
                *(float4*)(orow + c) = v;
            }
        }
        __syncwarp();

        // ---- O += P V (warp-private rows) ----
        {
            const int wr0 = wid * 16;
            wmma::fragment<wmma::accumulator, 16, 16, 16, float> acc[4];
            #pragma unroll
            for (int c = 0; c < 4; c++)
                wmma::load_matrix_sync(acc[c], Os + wr0 * SLD + c * 16,
                                       SLD, wmma::mem_row_major);
            #pragma unroll
            for (int ks = 0; ks < 4; ks++) {
                wmma::fragment<wmma::matrix_a, 16, 16, 16, half,
                               wmma::row_major> af;
                wmma::load_matrix_sync(af, Ps + wr0 * QLD + ks * 16, QLD);
                #pragma unroll
                for (int c = 0; c < 4; c++) {
                    wmma::fragment<wmma::matrix_b, 16, 16, 16, half,
                                   wmma::row_major> bf;
                    wmma::load_matrix_sync(bf, vb + (ks * 16) * QLD + c * 16, QLD);
                    wmma::mma_sync(acc[c], af, bf, acc[c]);
                }
            }
            #pragma unroll
            for (int c = 0; c < 4; c++)
                wmma::store_matrix_sync(Os + wr0 * SLD + c * 16, acc[c],
                                        SLD, wmma::mem_row_major);
        }
        __syncwarp();
    }
    __syncthreads();

    {
        int lg = q0 + r;
        if (lg < L_SEQ) {
            float inv_l = 1.0f / l_run;
            const float* orow = Os + r * SLD + cb0;
            __half2* dst = (__half2*)(aoh + (size_t)(b * L_SEQ + lg) * CDIM
                                      + h * HDIM + cb0);
            #pragma unroll
            for (int c = 0; c < 32; c += 2)
                dst[c >> 1] = __floats2half2_rn(orow[c] * inv_l,
                                                orow[c + 1] * inv_l);
        }
    }
}

// ---------------------------------------------------------------------------
extern "C" void kernel_launch(void* const* d_in, const int* in_sizes, int n_in,
                              void* d_out, int out_size)
{
    const float* x    = (const float*)d_in[0];
    const float* pos  = (const float*)d_in[1];
    const float* wqkv = (const float*)d_in[2];
    const float* qb   = (const float*)d_in[3];
    const float* vb   = (const float*)d_in[4];
    const float* wo   = (const float*)d_in[5];
    const float* bo   = (const float*)d_in[6];
    float* out = (float*)d_out;

    float *bias_p;
    __half *xh_p, *wqkvh_p, *woh_p, *qkvh_p, *aoh_p;
    cudaGetSymbolAddress((void**)&bias_p,  g_bias);
    cudaGetSymbolAddress((void**)&xh_p,    g_xh);
    cudaGetSymbolAddress((void**)&wqkvh_p, g_wqkvh);
    cudaGetSymbolAddress((void**)&woh_p,   g_woh);
    cudaGetSymbolAddress((void**)&qkvh_p,  g_qkvh);
    cudaGetSymbolAddress((void**)&aoh_p,   g_aoh);

    bias_compose_kernel<<<(QKVN + 255)/256, 256>>>(qb, vb);

    {
        int n4 = (MROWS * CDIM) / 4;
        round_half_kernel<<<(n4 + 255)/256, 256>>>(x, xh_p, n4);
        n4 = (QKVN * CDIM) / 4;
        round_half_kernel<<<(n4 + 255)/256, 256>>>(wqkv, wqkvh_p, n4);
        n4 = (CDIM * CDIM) / 4;
        round_half_kernel<<<(n4 + 255)/256, 256>>>(wo, woh_p, n4);
    }

    cudaFuncSetAttribute(gemm_fp16_bt_bias,
                         cudaFuncAttributeMaxDynamicSharedMemorySize, GEMM_SMEM_BYTES);

    dim3 g1(QKVN / GBN, (MROWS + GBM - 1) / GBM);
    gemm_fp16_bt_bias<<<g1, GEMM_THREADS, GEMM_SMEM_BYTES>>>(
        xh_p, wqkvh_p, bias_p, nullptr, qkvh_p, MROWS, QKVN, CDIM);

    {
        int total = MROWS * 2 * NHEADS * 8;
        rope_kernel<<<(total + 255)/256, 256>>>(pos, qkvh_p);
    }

    cudaFuncSetAttribute(attn_fp16_kernel,
                         cudaFuncAttributeMaxDynamicSharedMemorySize, ATT_SMEM_BYTES);
    attn_fp16_kernel<<<dim3((L_SEQ + AQ - 1)/AQ, NHEADS, BATCH), ATHREADS,
                       ATT_SMEM_BYTES>>>(qkvh_p, aoh_p);

    dim3 g2(CDIM / GBN, (MROWS + GBM - 1) / GBM);
    gemm_fp16_bt_bias<<<g2, GEMM_THREADS, GEMM_SMEM_BYTES>>>(
        aoh_p, woh_p, bo, out, nullptr, MROWS, CDIM, CDIM);
}

// round 17
// speedup vs baseline: 1.9874x; 1.2565x over previous
#include <cuda_runtime.h>
#include <cstdint>
#include <cuda_fp16.h>
#include <mma.h>
#include <math.h>

using namespace nvcuda;

#define BATCH   8
#define L_SEQ   680
#define NHEADS  24
#define HDIM    64
#define CDIM    1536
#define MROWS   (BATCH * L_SEQ)      // 5440
#define QKVN    (3 * CDIM)           // 4608

// ---------------- GEMM tiling (fp16 HMMA m16n16k16) — R12/R15 proven -------
#define GBM 256
#define GBN 128
#define HBK 32
#define NSTAGE 3
#define HTLD 40
#define SROWS (GBM + GBN)
#define STAGE_H (SROWS * HTLD)
#define EPLD 132
#define GEMM_THREADS 256
#define GEMM_SMEM_BYTES (NSTAGE * STAGE_H * 2)   // 92160

// ---------------- attention (FA2, mma.sync, register-resident S/P/O) -------
#define AQ 128
#define AK 64
#define QLD 72                       // halves; 144B rows (16B aligned)
#define ATHREADS 256
#define ATT_SMEM_BYTES ((AQ * QLD + 2 * AK * QLD + 2 * AK * QLD) * 2)  // 55296

__device__ float  g_bias[QKVN];
__device__ __half g_xh   [MROWS * CDIM];
__device__ __half g_wqkvh[QKVN * CDIM];
__device__ __half g_woh  [CDIM * CDIM];
__device__ __half g_qkvh [MROWS * QKVN];
__device__ __half g_aoh  [MROWS * CDIM];

// ---------------------------------------------------------------------------
__global__ void bias_compose_kernel(const float* __restrict__ qb,
                                    const float* __restrict__ vb) {
    int n = blockIdx.x * 256 + threadIdx.x;
    if (n >= QKVN) return;
    float v = 0.f;
    if (n < CDIM)            v = qb[n];
    else if (n >= 2 * CDIM)  v = vb[n - 2 * CDIM];
    g_bias[n] = v;
}

__global__ __launch_bounds__(256) void round_half_kernel(
    const float* __restrict__ x, __half* __restrict__ y, int n4)
{
    int i = blockIdx.x * 256 + threadIdx.x;
    if (i >= n4) return;
    float4 v = ((const float4*)x)[i];
    ((__half2*)y)[2 * i + 0] = __floats2half2_rn(v.x, v.y);
    ((__half2*)y)[2 * i + 1] = __floats2half2_rn(v.z, v.w);
}

// ---------------------------------------------------------------------------
__device__ __forceinline__ void cp_async16h(__half* smem, const __half* g, bool pred) {
    unsigned int saddr = (unsigned int)__cvta_generic_to_shared(smem);
    int sz = pred ? 16 : 0;
    asm volatile("cp.async.cg.shared.global [%0], [%1], 16, %2;\n"
                 :: "r"(saddr), "l"(g), "r"(sz));
}
__device__ __forceinline__ void cp_commit() {
    asm volatile("cp.async.commit_group;\n");
}
template <int N>
__device__ __forceinline__ void cp_wait() {
    asm volatile("cp.async.wait_group %0;\n" :: "n"(N));
}

__device__ __forceinline__ void ldmx4(uint32_t& r0, uint32_t& r1,
                                      uint32_t& r2, uint32_t& r3, uint32_t a) {
    asm volatile("ldmatrix.sync.aligned.m8n8.x4.shared.b16 {%0,%1,%2,%3}, [%4];\n"
                 : "=r"(r0), "=r"(r1), "=r"(r2), "=r"(r3) : "r"(a));
}
__device__ __forceinline__ void ldmx4t(uint32_t& r0, uint32_t& r1,
                                       uint32_t& r2, uint32_t& r3, uint32_t a) {
    asm volatile("ldmatrix.sync.aligned.m8n8.x4.trans.shared.b16 {%0,%1,%2,%3}, [%4];\n"
                 : "=r"(r0), "=r"(r1), "=r"(r2), "=r"(r3) : "r"(a));
}
__device__ __forceinline__ void mma16816(float* d, const uint32_t* a,
                                         const uint32_t* b) {
    asm volatile(
        "mma.sync.aligned.m16n8k16.row.col.f32.f16.f16.f32 "
        "{%0,%1,%2,%3}, {%4,%5,%6,%7}, {%8,%9}, {%0,%1,%2,%3};\n"
        : "+f"(d[0]), "+f"(d[1]), "+f"(d[2]), "+f"(d[3])
        : "r"(a[0]), "r"(a[1]), "r"(a[2]), "r"(a[3]), "r"(b[0]), "r"(b[1]));
}

// ---------------------------------------------------------------------------
// C[m][n] = sum_k A[m][k]*Bm[n][k] + bias[n] (fp16 HMMA, fp32 accum)
// [R12-proven; unchanged]
// ---------------------------------------------------------------------------
__global__ __launch_bounds__(GEMM_THREADS) void gemm_fp16_bt_bias(
    const __half* __restrict__ A, const __half* __restrict__ Bm,
    const float* __restrict__ bias, float* __restrict__ Cf,
    __half* __restrict__ Ch, int M, int N, int K)
{
    extern __shared__ __half smh[];
    float* smf = reinterpret_cast<float*>(smh);

    const int tid = threadIdx.x;
    const int wid = tid >> 5;
    const int m0  = blockIdx.y * GBM;
    const int n0  = blockIdx.x * GBN;
    const int wm  = wid >> 1;
    const int wn  = wid & 1;

    wmma::fragment<wmma::accumulator, 16, 16, 16, float> acc[4][4];
    #pragma unroll
    for (int i = 0; i < 4; i++)
        #pragma unroll
        for (int j = 0; j < 4; j++)
            wmma::fill_fragment(acc[i][j], 0.0f);

    const int nk = K / HBK;

    auto load_stage = [&](int s, int kc) {
        __half* base = smh + s * STAGE_H;
        #pragma unroll
        for (int r = 0; r < 6; r++) {
            int u    = tid + r * GEMM_THREADS;
            int row  = u >> 2;
            int slot = u & 3;
            __half* dst = base + row * HTLD + slot * 8;
            if (row < GBM) {
                cp_async16h(dst, A + (size_t)(m0 + row) * K + kc + slot * 8,
                            (m0 + row) < M);
            } else {
                cp_async16h(dst, Bm + (size_t)(n0 + row - GBM) * K + kc + slot * 8,
                            true);
            }
        }
    };

    load_stage(0, 0);        cp_commit();
    load_stage(1, HBK);      cp_commit();

    for (int kt = 0; kt < nk; kt++) {
        cp_wait<1>();
        __syncthreads();

        if (kt + 2 < nk) {
            load_stage((kt + 2) % NSTAGE, (kt + 2) * HBK);
            cp_commit();
        }

        const __half* ab = smh + (kt % NSTAGE) * STAGE_H;
        const __half* bb = ab + GBM * HTLD;

        #pragma unroll
        for (int ks = 0; ks < 2; ks++) {
            wmma::fragment<wmma::matrix_a, 16, 16, 16, half,
                           wmma::row_major> af[4];
            wmma::fragment<wmma::matrix_b, 16, 16, 16, half,
                           wmma::col_major> bf[4];
            #pragma unroll
            for (int i = 0; i < 4; i++)
                wmma::load_matrix_sync(af[i],
                    ab + (wm * 64 + i * 16) * HTLD + ks * 16, HTLD);
            #pragma unroll
            for (int j = 0; j < 4; j++)
                wmma::load_matrix_sync(bf[j],
                    bb + (wn * 64 + j * 16) * HTLD + ks * 16, HTLD);
            #pragma unroll
            for (int i = 0; i < 4; i++)
                #pragma unroll
                for (int j = 0; j < 4; j++)
                    wmma::mma_sync(acc[i][j], af[i], bf[j], acc[i][j]);
        }
    }

    #pragma unroll
    for (int pass = 0; pass < 2; pass++) {
        __syncthreads();
        if ((wm >> 1) == pass) {
            #pragma unroll
            for (int i = 0; i < 4; i++)
                #pragma unroll
                for (int j = 0; j < 4; j++)
                    wmma::store_matrix_sync(
                        smf + ((wm & 1) * 64 + i * 16) * EPLD + wn * 64 + j * 16,
                        acc[i][j], EPLD, wmma::mem_row_major);
        }
        __syncthreads();
        {
            int r = tid >> 1;
            int cseg = (tid & 1) * 64;
            int m = m0 + pass * 128 + r;
            if (m < M) {
                const float* ep = smf + r * EPLD + cseg;
                const float* bp = bias + n0 + cseg;
                if (Cf) {
                    float* cp = Cf + (size_t)m * N + n0 + cseg;
                    #pragma unroll
                    for (int j = 0; j < 16; j++) {
                        float4 v = *(const float4*)(ep + j * 4);
                        v.x += bp[j * 4 + 0]; v.y += bp[j * 4 + 1];
                        v.z += bp[j * 4 + 2]; v.w += bp[j * 4 + 3];
                        *(float4*)(cp + j * 4) = v;
                    }
                } else {
                    __half2* cp = (__half2*)(Ch + (size_t)m * N + n0 + cseg);
                    #pragma unroll
                    for (int j = 0; j < 16; j++) {
                        float4 v = *(const float4*)(ep + j * 4);
                        cp[2 * j + 0] = __floats2half2_rn(v.x + bp[j*4+0],
                                                          v.y + bp[j*4+1]);
                        cp[2 * j + 1] = __floats2half2_rn(v.z + bp[j*4+2],
                                                          v.w + bp[j*4+3]);
                    }
                }
            }
        }
    }
}

// ---------------------------------------------------------------------------
// RoPE in place over q and k components of g_qkvh (half in/out, fp32 math).
// ---------------------------------------------------------------------------
__global__ __launch_bounds__(256) void rope_kernel(
    const float* __restrict__ pos, __half* __restrict__ qkvh)
{
    int u = blockIdx.x * 256 + threadIdx.x;
    const int total = MROWS * 2 * NHEADS * 8;
    if (u >= total) return;
    int quad = u & 7;  u >>= 3;
    int h    = u % NHEADS; u /= NHEADS;
    int comp = u & 1;  int row = u >> 1;
    int d = quad * 4;

    __half* base = qkvh + (size_t)row * QKVN + comp * CDIM + h * HDIM;
    float p0 = pos[(size_t)row * 2 + 0];
    float p1 = pos[(size_t)row * 2 + 1];

    __half2 lo01 = *(__half2*)(base + d);
    __half2 lo23 = *(__half2*)(base + d + 2);
    __half2 hi01 = *(__half2*)(base + d + 32);
    __half2 hi23 = *(__half2*)(base + d + 32 + 2);
    float lo[4] = { __half2float(lo01.x), __half2float(lo01.y),
                    __half2float(lo23.x), __half2float(lo23.y) };
    float hi[4] = { __half2float(hi01.x), __half2float(hi01.y),
                    __half2float(hi23.x), __half2float(hi23.y) };
    float nlo[4], nhi[4];
    #pragma unroll
    for (int j = 0; j < 4; j++) {
        int fi = (d + j) & 15;
        float invf = __expf(-0.5756462732485115f * (float)fi);
        float sa, ca, sb, cb;
        __sincosf(p0 * invf, &sa, &ca);
        __sincosf(p1 * invf, &sb, &cb);
        nlo[j] = lo[j] * ca - hi[j] * sa;
        nhi[j] = hi[j] * cb + lo[j] * sb;
    }
    *(__half2*)(base + d)          = __floats2half2_rn(nlo[0], nlo[1]);
    *(__half2*)(base + d + 2)      = __floats2half2_rn(nlo[2], nlo[3]);
    *(__half2*)(base + d + 32)     = __floats2half2_rn(nhi[0], nhi[1]);
    *(__half2*)(base + d + 32 + 2) = __floats2half2_rn(nhi[2], nhi[3]);
}

// ---------------------------------------------------------------------------
// FA2 attention: mma.sync.m16n8k16, S/P/O register-resident.
// Warp w owns q rows q0+16w..+15. Only Q/K/V touch smem.
//
// Layout notes (verified against PTX fragment specs):
//  B-operand of m16n8k16.row.col needs lane j: (k=2*tig,+1; n=gid),
//  tig=lane&3, gid=lane>>2.
//  K smem [key][dim]: for S=QK^T, k-dim = head-dim, n = key. NON-trans
//  ldmatrix on key-rows gives (key=gid, dims 2*tig,+1) — exactly B. Pairs:
//  b={m0,m2} for keys 0-7, {m1,m3} for keys 8-15 (m-order: keylow/dimlow,
//  keyhigh/dimlow, keylow/dimhigh, keyhigh/dimhigh).
//  V smem [key][dim]: for PV, k = key, n = dim. TRANS ldmatrix gives
//  (key=2*tig,+1; dim=gid) — exactly B. Pairs: {m0,m1} dims 0-7, {m2,m3}.
// ---------------------------------------------------------------------------
__global__ __launch_bounds__(ATHREADS) void attn_fa2_kernel(
    const __half* __restrict__ qkvh, __half* __restrict__ aoh)
{
    extern __shared__ __half sma[];
    __half* Qs = sma;                        // [128][QLD]
    __half* Ks = sma + AQ * QLD;             // [2][64][QLD]
    __half* Vs = Ks + 2 * AK * QLD;          // [2][64][QLD]
    const uint32_t sQ = (uint32_t)__cvta_generic_to_shared(Qs);
    const uint32_t sK = (uint32_t)__cvta_generic_to_shared(Ks);
    const uint32_t sV = (uint32_t)__cvta_generic_to_shared(Vs);

    const int qt = blockIdx.x, h = blockIdx.y, b = blockIdx.z;
    const int tid = threadIdx.x;
    const int wid = tid >> 5;
    const int lane = tid & 31;
    const int q0  = qt * AQ;
    const int wr0 = wid * 16;

    #pragma unroll
    for (int c = 0; c < 4; c++) {
        int u = tid + c * ATHREADS;
        int row = u >> 3, slot = u & 7;
        int lg = q0 + row;
        cp_async16h(Qs + row * QLD + slot * 8,
                    qkvh + (size_t)(b * L_SEQ + (lg < L_SEQ ? lg : 0)) * QKVN
                         + h * HDIM + slot * 8,
                    lg < L_SEQ);
    }
    cp_commit();

    auto load_kv = [&](int bf, int k0) {
        __half* kd = Ks + bf * AK * QLD;
        __half* vd = Vs + bf * AK * QLD;
        #pragma unroll
        for (int c = 0; c < 2; c++) {
            int u = tid + c * ATHREADS;
            int row = u >> 3, slot = u & 7;
            int lg = k0 + row;
            bool ok = lg < L_SEQ;
            size_t gro = (size_t)(b * L_SEQ + (ok ? lg : 0)) * QKVN + h * HDIM
                         + slot * 8;
            cp_async16h(kd + row * QLD + slot * 8, qkvh + gro + CDIM, ok);
            cp_async16h(vd + row * QLD + slot * 8, qkvh + gro + 2 * CDIM, ok);
        }
    };
    load_kv(0, 0);
    cp_commit();

    float of[8][4];
    #pragma unroll
    for (int j = 0; j < 8; j++)
        #pragma unroll
        for (int c = 0; c < 4; c++) of[j][c] = 0.f;
    float m_run0 = -1e30f, m_run1 = -1e30f;
    float l_run0 = 0.f,    l_run1 = 0.f;

    cp_wait<0>();
    __syncthreads();              // Q, K0, V0 resident

    uint32_t qf[4][4];
    {
        int row = wr0 + (lane & 15);
        int colh = (lane >> 4) * 8;
        #pragma unroll
        for (int kf = 0; kf < 4; kf++)
            ldmx4(qf[kf][0], qf[kf][1], qf[kf][2], qf[kf][3],
                  sQ + (uint32_t)(row * QLD + kf * 16 + colh) * 2);
    }

    const int lrow = ((lane >> 3) & 1) * 8 + (lane & 7);
    const int lcol = ((lane >> 4) & 1) * 8;
    const int kc   = (lane & 3) * 2;

    const int NT = (L_SEQ + AK - 1) / AK;   // 11
    for (int kt = 0; kt < NT; kt++) {
        int k0 = kt * AK;
        if (kt + 1 < NT) {
            load_kv((kt + 1) & 1, k0 + AK);
            cp_commit();
        }

        const uint32_t kb = sK + (uint32_t)((kt & 1) * AK * QLD) * 2;
        const uint32_t vb = sV + (uint32_t)((kt & 1) * AK * QLD) * 2;

        // ---- S = Q K^T (register accum) ----
        float sacc[8][4];
        #pragma unroll
        for (int j = 0; j < 8; j++)
            #pragma unroll
            for (int c = 0; c < 4; c++) sacc[j][c] = 0.f;

        #pragma unroll
        for (int jp = 0; jp < 4; jp++) {
            #pragma unroll
            for (int kf = 0; kf < 4; kf++) {
                uint32_t r0, r1, r2, r3;
                // NON-trans: K rows are keys; fragment = exact B operand
                ldmx4(r0, r1, r2, r3,
                      kb + (uint32_t)((16 * jp + lrow) * QLD + kf * 16 + lcol) * 2);
                uint32_t bA[2] = { r0, r2 };   // keys 16jp+0..7
                uint32_t bB[2] = { r1, r3 };   // keys 16jp+8..15
                mma16816(sacc[2 * jp],     qf[kf], bA);
                mma16816(sacc[2 * jp + 1], qf[kf], bB);
            }
        }

        // ---- softmax (register; rows r0=wr0+(lane>>2), r1=r0+8) ----
        float mx0 = -1e30f, mx1 = -1e30f;
        #pragma unroll
        for (int j = 0; j < 8; j++) {
            int kg = k0 + 8 * j + kc;
            float s0 = sacc[j][0] * 0.125f; if (kg     >= L_SEQ) s0 = -1e30f;
            float s1 = sacc[j][1] * 0.125f; if (kg + 1 >= L_SEQ) s1 = -1e30f;
            float s2 = sacc[j][2] * 0.125f; if (kg     >= L_SEQ) s2 = -1e30f;
            float s3 = sacc[j][3] * 0.125f; if (kg + 1 >= L_SEQ) s3 = -1e30f;
            sacc[j][0] = s0; sacc[j][1] = s1; sacc[j][2] = s2; sacc[j][3] = s3;
            mx0 = fmaxf(mx0, fmaxf(s0, s1));
            mx1 = fmaxf(mx1, fmaxf(s2, s3));
        }
        mx0 = fmaxf(mx0, __shfl_xor_sync(0xffffffffu, mx0, 1));
        mx0 = fmaxf(mx0, __shfl_xor_sync(0xffffffffu, mx0, 2));
        mx1 = fmaxf(mx1, __shfl_xor_sync(0xffffffffu, mx1, 1));
        mx1 = fmaxf(mx1, __shfl_xor_sync(0xffffffffu, mx1, 2));

        float m_new0 = fmaxf(m_run0, mx0);
        float m_new1 = fmaxf(m_run1, mx1);
        float alpha0 = __expf(m_run0 - m_new0);
        float alpha1 = __expf(m_run1 - m_new1);

        uint32_t ph[8][2];
        float rsum0 = 0.f, rsum1 = 0.f;
        #pragma unroll
        for (int j = 0; j < 8; j++) {
            float p0 = __expf(sacc[j][0] - m_new0);
            float p1 = __expf(sacc[j][1] - m_new0);
            float p2 = __expf(sacc[j][2] - m_new1);
            float p3 = __expf(sacc[j][3] - m_new1);
            rsum0 += p0 + p1;
            rsum1 += p2 + p3;
            __half2 h01 = __floats2half2_rn(p0, p1);
            __half2 h23 = __floats2half2_rn(p2, p3);
            ph[j][0] = *(uint32_t*)&h01;
            ph[j][1] = *(uint32_t*)&h23;
        }
        rsum0 += __shfl_xor_sync(0xffffffffu, rsum0, 1);
        rsum0 += __shfl_xor_sync(0xffffffffu, rsum0, 2);
        rsum1 += __shfl_xor_sync(0xffffffffu, rsum1, 1);
        rsum1 += __shfl_xor_sync(0xffffffffu, rsum1, 2);

        l_run0 = l_run0 * alpha0 + rsum0;
        l_run1 = l_run1 * alpha1 + rsum1;
        m_run0 = m_new0;
        m_run1 = m_new1;

        #pragma unroll
        for (int j = 0; j < 8; j++) {
            of[j][0] *= alpha0; of[j][1] *= alpha0;
            of[j][2] *= alpha1; of[j][3] *= alpha1;
        }

        // ---- O += P V (P accum reused as A operand; V needs trans) ----
        #pragma unroll
        for (int f = 0; f < 4; f++) {
            uint32_t af[4] = { ph[2*f][0], ph[2*f][1], ph[2*f+1][0], ph[2*f+1][1] };
            #pragma unroll
            for (int dp = 0; dp < 4; dp++) {
                uint32_t r0, r1, r2, r3;
                ldmx4t(r0, r1, r2, r3,
                       vb + (uint32_t)((16 * f + lrow) * QLD + dp * 16 + lcol) * 2);
                uint32_t bA[2] = { r0, r1 };   // dims 16dp+0..7
                uint32_t bB[2] = { r2, r3 };   // dims 16dp+8..15
                mma16816(of[2 * dp],     af, bA);
                mma16816(of[2 * dp + 1], af, bB);
            }
        }

        if (kt + 1 < NT) {
            cp_wait<0>();
            __syncthreads();
        }
    }

    // ---- writeout: /l, half ----
    {
        int r0g = q0 + wr0 + (lane >> 2);
        int r1g = r0g + 8;
        float il0 = 1.0f / l_run0;
        float il1 = 1.0f / l_run1;
        #pragma unroll
        for (int j = 0; j < 8; j++) {
            int dcol = h * HDIM + 8 * j + kc;
            if (r0g < L_SEQ) {
                __half2 v = __floats2half2_rn(of[j][0] * il0, of[j][1] * il0);
                *(__half2*)(aoh + (size_t)(b * L_SEQ + r0g) * CDIM + dcol) = v;
            }
            if (r1g < L_SEQ) {
                __half2 v = __floats2half2_rn(of[j][2] * il1, of[j][3] * il1);
                *(__half2*)(aoh + (size_t)(b * L_SEQ + r1g) * CDIM + dcol) = v;
            }
        }
    }
}

// ---------------------------------------------------------------------------
extern "C" void kernel_launch(void* const* d_in, const int* in_sizes, int n_in,
                              void* d_out, int out_size)
{
    const float* x    = (const float*)d_in[0];
    const float* pos  = (const float*)d_in[1];
    const float* wqkv = (const float*)d_in[2];
    const float* qb   = (const float*)d_in[3];
    const float* vb   = (const float*)d_in[4];
    const float* wo   = (const float*)d_in[5];
    const float* bo   = (const float*)d_in[6];
    float* out = (float*)d_out;

    float *bias_p;
    __half *xh_p, *wqkvh_p, *woh_p, *qkvh_p, *aoh_p;
    cudaGetSymbolAddress((void**)&bias_p,  g_bias);
    cudaGetSymbolAddress((void**)&xh_p,    g_xh);
    cudaGetSymbolAddress((void**)&wqkvh_p, g_wqkvh);
    cudaGetSymbolAddress((void**)&woh_p,   g_woh);
    cudaGetSymbolAddress((void**)&qkvh_p,  g_qkvh);
    cudaGetSymbolAddress((void**)&aoh_p,   g_aoh);

    bias_compose_kernel<<<(QKVN + 255)/256, 256>>>(qb, vb);

    {
        int n4 = (MROWS * CDIM) / 4;
        round_half_kernel<<<(n4 + 255)/256, 256>>>(x, xh_p, n4);
        n4 = (QKVN * CDIM) / 4;
        round_half_kernel<<<(n4 + 255)/256, 256>>>(wqkv, wqkvh_p, n4);
        n4 = (CDIM * CDIM) / 4;
        round_half_kernel<<<(n4 + 255)/256, 256>>>(wo, woh_p, n4);
    }

    cudaFuncSetAttribute(gemm_fp16_bt_bias,
                         cudaFuncAttributeMaxDynamicSharedMemorySize, GEMM_SMEM_BYTES);

    dim3 g1(QKVN / GBN, (MROWS + GBM - 1) / GBM);
    gemm_fp16_bt_bias<<<g1, GEMM_THREADS, GEMM_SMEM_BYTES>>>(
        xh_p, wqkvh_p, bias_p, nullptr, qkvh_p, MROWS, QKVN, CDIM);

    {
        int total = MROWS * 2 * NHEADS * 8;
        rope_kernel<<<(total + 255)/256, 256>>>(pos, qkvh_p);
    }

    cudaFuncSetAttribute(attn_fa2_kernel,
                         cudaFuncAttributeMaxDynamicSharedMemorySize, ATT_SMEM_BYTES);
    attn_fa2_kernel<<<dim3((L_SEQ + AQ - 1)/AQ, NHEADS, BATCH), ATHREADS,
                      ATT_SMEM_BYTES>>>(qkvh_p, aoh_p);

    dim3 g2(CDIM / GBN, (MROWS + GBM - 1) / GBM);
    gemm_fp16_bt_bias<<<g2, GEMM_THREADS, GEMM_SMEM_BYTES>>>(
        aoh_p, woh_p, bo, out, nullptr, MROWS, CDIM, CDIM);
}